// round 12
// baseline (speedup 1.0000x reference)
#include <cuda_runtime.h>
#include <cuda_fp16.h>
#include <cstdint>
#include <math.h>

#define BB   16
#define TT   24
#define HH   96
#define WW   96
#define CIN  16
#define FF   16
#define GG   64

#define TLX  32
#define TLY  8
#define STATE_ELEMS (BB * HH * WW * FF)
#define XN (BB * TT * HH * WW * CIN)

// ---------------- device global scratch ----------------
__device__ __align__(16) __half g_x[XN];
__device__ __align__(16) __half g_h[2][STATE_ELEMS];
__device__ __align__(16) float  g_c[STATE_ELEMS];
// B fragments: [kstep 18][ntile 8][lane 32][word 4] : word = {bh0,bh1,bl0,bl1}
// weights kept as fp16 hi+lo pair (accurate to ~2^-22)
#define BFRAG_WORDS (18 * 8 * 32 * 4)   // 18432 words = 72KB
__device__ __align__(16) uint32_t g_bfrag[BFRAG_WORDS];

// ---------------- smem layout (bytes) ----------------
// [0 : 73728)  B fragment table (copied once per block; L1 is flushed per
//              launch so direct LDG would re-pay L2 latency every step)
// [73728 : +2*10880)  strips: x, h ; each [row 10][col 34][ci 16] fp16
// XOR-swizzled: pixel pi stores its two 16B halves at pi*32 + (half ^ ((pi&4)<<2))
#define BF_BYTES    73728
#define STRIP_BYTES (10 * 34 * CIN * 2)     // 10880
#define SMEM_TOTAL  (BF_BYTES + 2 * STRIP_BYTES)   // 95488

// ---------------- mma / ldmatrix helpers ----------------
__device__ __forceinline__ void mma16816(float* d, const uint32_t* a,
                                         uint32_t b0, uint32_t b1) {
    asm volatile(
        "mma.sync.aligned.m16n8k16.row.col.f32.f16.f16.f32 "
        "{%0,%1,%2,%3}, {%4,%5,%6,%7}, {%8,%9}, {%0,%1,%2,%3};"
        : "+f"(d[0]), "+f"(d[1]), "+f"(d[2]), "+f"(d[3])
        : "r"(a[0]), "r"(a[1]), "r"(a[2]), "r"(a[3]), "r"(b0), "r"(b1));
}
__device__ __forceinline__ void ldsm_x4(uint32_t* a, uint32_t addr) {
    asm volatile(
        "ldmatrix.sync.aligned.m8n8.x4.shared.b16 {%0,%1,%2,%3}, [%4];"
        : "=r"(a[0]), "=r"(a[1]), "=r"(a[2]), "=r"(a[3]) : "r"(addr));
}
__device__ __forceinline__ uint32_t smem_u32(const void* p) {
    uint32_t a;
    asm("{ .reg .u64 t; cvta.to.shared.u64 t, %1; cvt.u32.u64 %0, t; }"
        : "=r"(a) : "l"(p));
    return a;
}

// ---------------- setup kernels ----------------
__global__ void convert_x_kernel(const float* __restrict__ x) {
    for (long i = blockIdx.x * (long)blockDim.x + threadIdx.x; i < XN;
         i += (long)gridDim.x * blockDim.x) {
        g_x[i] = __float2half_rn(x[i]);
    }
}

__global__ void zero_state_kernel() {
    __half z = __float2half_rn(0.f);
    for (int i = blockIdx.x * blockDim.x + threadIdx.x; i < STATE_ELEMS;
         i += gridDim.x * blockDim.x) {
        g_h[0][i] = z;
        g_c[i] = 0.f;
    }
}

__global__ void bfrag_kernel(const float* __restrict__ wx,
                             const float* __restrict__ wh) {
    int idx = blockIdx.x * blockDim.x + threadIdx.x;
    if (idx >= BFRAG_WORDS) return;
    int w     = idx & 3;           // 0:bh0 1:bh1 2:bl0 3:bl1
    int lane  = (idx >> 2) & 31;
    int nt    = (idx >> 7) & 7;
    int kstep = idx >> 10;
    int part = w >> 1;
    int reg  = w & 1;
    int j = lane & 3;
    int n = nt * 8 + (lane >> 2);
    int k0 = reg * 8 + 2 * j;
    const float* W = (kstep < 9) ? wx : wh;
    int tap = (kstep < 9) ? kstep : kstep - 9;
    float v0 = W[(tap * 16 + k0) * 64 + n];
    float v1 = W[(tap * 16 + k0 + 1) * 64 + n];
    __half h0 = __float2half_rn(v0);
    __half h1 = __float2half_rn(v1);
    __half o0, o1;
    if (part == 0) { o0 = h0; o1 = h1; }
    else {
        o0 = __float2half_rn(v0 - __half2float(h0));
        o1 = __float2half_rn(v1 - __half2float(h1));
    }
    uint32_t word = (uint32_t)__half_as_ushort(o0) |
                    ((uint32_t)__half_as_ushort(o1) << 16);
    g_bfrag[idx] = word;
}

// ---------------- main step kernel ----------------
__global__ __launch_bounds__(256, 2)
void lstm_step_mma(const float* __restrict__ bias,
                   const __half* __restrict__ h_in,
                   __half* __restrict__ h_out,
                   float* __restrict__ c_state,
                   int t)
{
    extern __shared__ char smem[];
    const uint32_t sb = smem_u32(smem);
    const int tid  = threadIdx.x;
    const int wid  = tid >> 5;
    const int lane = tid & 31;
    const int x0 = blockIdx.x * TLX;
    const int y0 = blockIdx.y * TLY;
    const int b  = blockIdx.z;

    // ---- stage B fragment table into smem (reused by all 8 warps, all
    //      18 ksteps; avoids per-launch L1-flush L2 latency on every LDG) ----
    {
        const uint4* src = (const uint4*)g_bfrag;
        uint4* dst = (uint4*)smem;
        #pragma unroll 1
        for (int i = tid; i < BF_BYTES / 16; i += 256) dst[i] = src[i];
    }

    // ---- stage strips (zero halo), XOR-swizzled 16B halves ----
    {
        const long xg = ((long)(b * TT + t)) * (HH * WW * CIN);
        const long hg = ((long)b) * (HH * WW * CIN);
        #pragma unroll 1
        for (int i = tid; i < 2 * 10 * 34; i += 256) {
            int comp = i / 340;          // 0: x, 1: h
            int idx  = i - comp * 340;
            int row  = idx / 34;
            int col  = idx - row * 34;
            int y  = y0 + row - 1;
            int xc = x0 + col - 1;
            uint4 v0 = make_uint4(0, 0, 0, 0), v1 = v0;
            if ((unsigned)y < HH && (unsigned)xc < WW) {
                const __half* base = comp ? h_in : g_x;
                long off = (comp ? hg : xg) + (((long)y) * WW + xc) * CIN;
                const uint4* sp = (const uint4*)(base + off);
                v0 = sp[0];
                v1 = sp[1];
            }
            int pi = row * 34 + col;
            int sw = (pi & 4) << 2;   // 0 or 16
            char* dp = smem + BF_BYTES + comp * STRIP_BYTES + pi * 32;
            *(uint4*)(dp + (0  ^ sw)) = v0;
            *(uint4*)(dp + (16 ^ sw)) = v1;
        }
    }
    __syncthreads();

    // ---- per-warp GEMM: m32 pixels x n64 gates, K=288, 2 products ----
    // z = sum A_fp16 * (Whi + Wlo)  -- exact GEMM of quantized activations
    const int prow = wid;                  // warp = image row within tile (0..7)
    const int g = lane >> 2;
    const int j = lane & 3;
    const int lcol  = lane & 15;           // ldmatrix pixel within m16 tile
    const int koff0 = lane & 16;           // ldmatrix k-half (bytes)

    float d[2][8][4];
    #pragma unroll
    for (int mt = 0; mt < 2; mt++)
        #pragma unroll
        for (int nt = 0; nt < 8; nt++)
            #pragma unroll
            for (int q = 0; q < 4; q++) d[mt][nt][q] = 0.f;

    // warp phase rotation: desynchronize the 4 warps per SMSP
    const int phase = (wid & 3) * 5;       // 0,5,10,15

    #pragma unroll 1
    for (int kk = 0; kk < 18; kk++) {
        int ks = kk + phase;
        if (ks >= 18) ks -= 18;
        const int tensorSel = (ks >= 9) ? 1 : 0;
        const int tap = ks - tensorSel * 9;
        const uint32_t shi = sb + BF_BYTES + tensorSel * STRIP_BYTES;

        const int dy = tap / 3;
        const int dx = tap - dy * 3;
        const int pi0 = (prow + dy) * 34 + (dx + lcol);        // mtile 0
        const int pi1 = pi0 + 16;                              // mtile 1
        const uint32_t a0 =
            (uint32_t)(pi0 * 32 + (koff0 ^ ((pi0 & 4) << 2)));
        const uint32_t a1 =
            (uint32_t)(pi1 * 32 + (koff0 ^ ((pi1 & 4) << 2)));

        uint32_t ah0[4], ah1[4];
        ldsm_x4(ah0, shi + a0);
        ldsm_x4(ah1, shi + a1);

        // B from smem: conflict-free LDS.128 (16B/lane, 512B per access)
        const char* bb = smem + ks * 4096 + lane * 16;
        #pragma unroll
        for (int p = 0; p < 4; p++) {
            const int n0 = 2 * p;
            const int n1 = 2 * p + 1;
            uint4 b0 = *(const uint4*)(bb + n0 * 512);
            uint4 b1 = *(const uint4*)(bb + n1 * 512);
            mma16816(d[0][n0], ah0, b0.x, b0.y);   // A * Whi
            mma16816(d[1][n0], ah1, b0.x, b0.y);
            mma16816(d[0][n1], ah0, b1.x, b1.y);
            mma16816(d[1][n1], ah1, b1.x, b1.y);
            mma16816(d[0][n0], ah0, b0.z, b0.w);   // A * Wlo
            mma16816(d[1][n0], ah1, b0.z, b0.w);
            mma16816(d[0][n1], ah0, b1.z, b1.w);
            mma16816(d[1][n1], ah1, b1.z, b1.w);
        }
    }

    // ---- epilogue: LSTM update, fully register-local per lane ----
    const int ybase = y0 + prow;
    #pragma unroll
    for (int mt = 0; mt < 2; mt++) {
        #pragma unroll
        for (int ph = 0; ph < 2; ph++) {            // pixel g or g+8
            const int xc = x0 + mt * 16 + g + ph * 8;
            const long pb = (((long)b * HH + ybase) * WW + xc) * FF;
            const int co = ph * 2;                  // accumulator index base
            #pragma unroll
            for (int pr = 0; pr < 2; pr++) {        // channel pair A / B
                const int ch  = pr * 8 + 2 * j;     // channels ch, ch+1
                const int ntb = pr;                 // gate ntiles: ntb, +2, +4, +6
                float zi0 = d[mt][ntb][co]       + __ldg(bias + ch);
                float zi1 = d[mt][ntb][co + 1]   + __ldg(bias + ch + 1);
                float zf0 = d[mt][ntb + 2][co]   + __ldg(bias + 16 + ch);
                float zf1 = d[mt][ntb + 2][co+1] + __ldg(bias + 16 + ch + 1);
                float zc0 = d[mt][ntb + 4][co]   + __ldg(bias + 32 + ch);
                float zc1 = d[mt][ntb + 4][co+1] + __ldg(bias + 32 + ch + 1);
                float zo0 = d[mt][ntb + 6][co]   + __ldg(bias + 48 + ch);
                float zo1 = d[mt][ntb + 6][co+1] + __ldg(bias + 48 + ch + 1);

                float2 cp = *(const float2*)(c_state + pb + ch);
                float ig0 = 1.f / (1.f + __expf(-zi0));
                float ig1 = 1.f / (1.f + __expf(-zi1));
                float fg0 = 1.f / (1.f + __expf(-zf0));
                float fg1 = 1.f / (1.f + __expf(-zf1));
                float og0 = 1.f / (1.f + __expf(-zo0));
                float og1 = 1.f / (1.f + __expf(-zo1));
                float cn0 = fg0 * cp.x + ig0 * fmaxf(zc0, 0.f);
                float cn1 = fg1 * cp.y + ig1 * fmaxf(zc1, 0.f);
                float hn0 = og0 * fmaxf(cn0, 0.f);
                float hn1 = og1 * fmaxf(cn1, 0.f);

                *(float2*)(c_state + pb + ch) = make_float2(cn0, cn1);

                __half hh0 = __float2half_rn(hn0);
                __half hh1 = __float2half_rn(hn1);
                uint32_t whv = (uint32_t)__half_as_ushort(hh0) |
                               ((uint32_t)__half_as_ushort(hh1) << 16);
                *(uint32_t*)(h_out + pb + ch) = whv;
            }
        }
    }
}

// ---------------- dense head ----------------
__global__ void dense_kernel(const __half* __restrict__ h,
                             const float* __restrict__ dw,
                             const float* __restrict__ db,
                             float* __restrict__ out)
{
    int idx = blockIdx.x * blockDim.x + threadIdx.x;
    if (idx >= BB * HH * WW) return;
    const __half* hp = h + (long)idx * FF;
    float sum = 0.f;
    #pragma unroll
    for (int k = 0; k < FF; k++) {
        sum += __half2float(hp[k]) * __ldg(dw + k);
    }
    out[idx] = sum + __ldg(db);
}

extern "C" void kernel_launch(void* const* d_in, const int* in_sizes, int n_in,
                              void* d_out, int out_size)
{
    (void)in_sizes; (void)n_in; (void)out_size;
    const float* x    = (const float*)d_in[0];
    const float* wx   = (const float*)d_in[1];
    const float* wh   = (const float*)d_in[2];
    const float* bias = (const float*)d_in[3];
    const float* dw   = (const float*)d_in[4];
    const float* db   = (const float*)d_in[5];
    float* out = (float*)d_out;

    cudaFuncSetAttribute(lstm_step_mma,
                         cudaFuncAttributeMaxDynamicSharedMemorySize, SMEM_TOTAL);

    __half* hbuf;
    float* cbuf;
    cudaGetSymbolAddress((void**)&hbuf, g_h);
    cudaGetSymbolAddress((void**)&cbuf, g_c);

    convert_x_kernel<<<2048, 256>>>(x);
    zero_state_kernel<<<512, 256>>>();
    bfrag_kernel<<<(BFRAG_WORDS + 255) / 256, 256>>>(wx, wh);

    dim3 grid(WW / TLX, HH / TLY, BB);   // (3, 12, 16)
    for (int t = 0; t < TT; t++) {
        __half* hin  = hbuf + (t & 1) * STATE_ELEMS;
        __half* hout = hbuf + ((t + 1) & 1) * STATE_ELEMS;
        lstm_step_mma<<<grid, 256, SMEM_TOTAL>>>(
            bias, hin, hout, cbuf, t);
    }

    // t=23 -> final h in buffer index 0
    int npix = BB * HH * WW;
    dense_kernel<<<(npix + 255) / 256, 256>>>(hbuf, dw, db, out);
}

// round 13
// speedup vs baseline: 1.1394x; 1.1394x over previous
#include <cuda_runtime.h>
#include <cuda_fp16.h>
#include <cstdint>
#include <math.h>

#define BB   16
#define TT   24
#define HH   96
#define WW   96
#define CIN  16
#define FF   16
#define GG   64

#define TLX  32
#define TLY  4
#define STATE_ELEMS (BB * HH * WW * FF)
#define XN (BB * TT * HH * WW * CIN)

// ---------------- device global scratch ----------------
__device__ __align__(16) __half g_x[XN];
__device__ __align__(16) __half g_h[2][STATE_ELEMS];
__device__ __align__(16) float  g_c[STATE_ELEMS];
// B fragments: [kstep 18][ntile 8][lane 32] uint4 = {bh0,bh1,bl0,bl1}
// weights kept as fp16 hi+lo pair (accurate to ~2^-22)
#define BFRAG_WORDS (18 * 8 * 32 * 4)   // 72KB, L1-resident within a launch
__device__ __align__(16) uint32_t g_bfrag[BFRAG_WORDS];

// ---------------- smem layout (bytes) ----------------
// 2 strips: x, h ; each [row 6][col 34][ci 16] fp16
// XOR-swizzled: pixel pi stores its two 16B halves at pi*32 + (half ^ ((pi&4)<<2))
#define STRIP_BYTES (6 * 34 * CIN * 2)      // 6528
#define SMEM_TOTAL  (2 * STRIP_BYTES)       // 13056

// ---------------- mma / ldmatrix helpers ----------------
__device__ __forceinline__ void mma16816(float* d, const uint32_t* a,
                                         uint32_t b0, uint32_t b1) {
    asm volatile(
        "mma.sync.aligned.m16n8k16.row.col.f32.f16.f16.f32 "
        "{%0,%1,%2,%3}, {%4,%5,%6,%7}, {%8,%9}, {%0,%1,%2,%3};"
        : "+f"(d[0]), "+f"(d[1]), "+f"(d[2]), "+f"(d[3])
        : "r"(a[0]), "r"(a[1]), "r"(a[2]), "r"(a[3]), "r"(b0), "r"(b1));
}
__device__ __forceinline__ void ldsm_x4(uint32_t* a, uint32_t addr) {
    asm volatile(
        "ldmatrix.sync.aligned.m8n8.x4.shared.b16 {%0,%1,%2,%3}, [%4];"
        : "=r"(a[0]), "=r"(a[1]), "=r"(a[2]), "=r"(a[3]) : "r"(addr));
}
__device__ __forceinline__ uint32_t smem_u32(const void* p) {
    uint32_t a;
    asm("{ .reg .u64 t; cvta.to.shared.u64 t, %1; cvt.u32.u64 %0, t; }"
        : "=r"(a) : "l"(p));
    return a;
}

// ---------------- setup kernels ----------------
__global__ void convert_x_kernel(const float* __restrict__ x) {
    for (long i = blockIdx.x * (long)blockDim.x + threadIdx.x; i < XN;
         i += (long)gridDim.x * blockDim.x) {
        g_x[i] = __float2half_rn(x[i]);
    }
}

__global__ void zero_state_kernel() {
    __half z = __float2half_rn(0.f);
    for (int i = blockIdx.x * blockDim.x + threadIdx.x; i < STATE_ELEMS;
         i += gridDim.x * blockDim.x) {
        g_h[0][i] = z;
        g_c[i] = 0.f;
    }
}

__global__ void bfrag_kernel(const float* __restrict__ wx,
                             const float* __restrict__ wh) {
    int idx = blockIdx.x * blockDim.x + threadIdx.x;
    if (idx >= BFRAG_WORDS) return;
    int w     = idx & 3;           // 0:bh0 1:bh1 2:bl0 3:bl1
    int lane  = (idx >> 2) & 31;
    int nt    = (idx >> 7) & 7;
    int kstep = idx >> 10;
    int part = w >> 1;
    int reg  = w & 1;
    int j = lane & 3;
    int n = nt * 8 + (lane >> 2);
    int k0 = reg * 8 + 2 * j;
    const float* W = (kstep < 9) ? wx : wh;
    int tap = (kstep < 9) ? kstep : kstep - 9;
    float v0 = W[(tap * 16 + k0) * 64 + n];
    float v1 = W[(tap * 16 + k0 + 1) * 64 + n];
    __half h0 = __float2half_rn(v0);
    __half h1 = __float2half_rn(v1);
    __half o0, o1;
    if (part == 0) { o0 = h0; o1 = h1; }
    else {
        o0 = __float2half_rn(v0 - __half2float(h0));
        o1 = __float2half_rn(v1 - __half2float(h1));
    }
    uint32_t word = (uint32_t)__half_as_ushort(o0) |
                    ((uint32_t)__half_as_ushort(o1) << 16);
    g_bfrag[idx] = word;
}

// ---------------- main step kernel ----------------
// 256 thr = 8 warps; warp = (image row, N-half): m32 x n32 per warp.
// 3 blocks/SM -> 24 warps/SM = 6 per SMSP for tensor-pipe latency hiding.
__global__ __launch_bounds__(256, 3)
void lstm_step_mma(const float* __restrict__ bias,
                   const __half* __restrict__ h_in,
                   __half* __restrict__ h_out,
                   float* __restrict__ c_state,
                   int t)
{
    extern __shared__ char smem[];
    const uint32_t sb = smem_u32(smem);
    const int tid  = threadIdx.x;
    const int wid  = tid >> 5;
    const int lane = tid & 31;
    const int x0 = blockIdx.x * TLX;
    const int y0 = blockIdx.y * TLY;
    const int b  = blockIdx.z;

    // ---- stage strips (zero halo), XOR-swizzled 16B halves ----
    {
        const long xg = ((long)(b * TT + t)) * (HH * WW * CIN);
        const long hg = ((long)b) * (HH * WW * CIN);
        #pragma unroll 1
        for (int i = tid; i < 2 * 6 * 34; i += 256) {
            int comp = i / 204;          // 0: x, 1: h
            int idx  = i - comp * 204;
            int row  = idx / 34;
            int col  = idx - row * 34;
            int y  = y0 + row - 1;
            int xc = x0 + col - 1;
            uint4 v0 = make_uint4(0, 0, 0, 0), v1 = v0;
            if ((unsigned)y < HH && (unsigned)xc < WW) {
                const __half* base = comp ? h_in : g_x;
                long off = (comp ? hg : xg) + (((long)y) * WW + xc) * CIN;
                const uint4* sp = (const uint4*)(base + off);
                v0 = sp[0];
                v1 = sp[1];
            }
            int pi = row * 34 + col;
            int sw = (pi & 4) << 2;   // 0 or 16
            char* dp = smem + comp * STRIP_BYTES + pi * 32;
            *(uint4*)(dp + (0  ^ sw)) = v0;
            *(uint4*)(dp + (16 ^ sw)) = v1;
        }
    }
    __syncthreads();

    // ---- per-warp GEMM: m32 pixels x n32 gates, K=288, 2 products ----
    // z = sum A_fp16 * (Whi + Wlo)  -- exact GEMM of quantized activations
    const int prow  = wid >> 1;            // image row within tile (0..3)
    const int nhalf = wid & 1;             // N-half: even/odd ntiles
    const int g = lane >> 2;
    const int j = lane & 3;
    const int lcol  = lane & 15;           // ldmatrix pixel within m16 tile
    const int koff0 = lane & 16;           // ldmatrix k-half (bytes)

    float d[2][4][4];                      // [mtile][gate p][quad]
    #pragma unroll
    for (int mt = 0; mt < 2; mt++)
        #pragma unroll
        for (int p = 0; p < 4; p++)
            #pragma unroll
            for (int q = 0; q < 4; q++) d[mt][p][q] = 0.f;

    // warp phase rotation: desynchronize warps sharing an SMSP
    int phase = wid * 5;
    if (phase >= 18) phase -= 18;          // {0,5,10,15,2,7,12,17}

    #pragma unroll 1
    for (int kk = 0; kk < 18; kk++) {
        int ks = kk + phase;
        if (ks >= 18) ks -= 18;
        const int tensorSel = (ks >= 9) ? 1 : 0;
        const int tap = ks - tensorSel * 9;
        const uint32_t shi = sb + tensorSel * STRIP_BYTES;

        const int dy = tap / 3;
        const int dx = tap - dy * 3;
        const int pi0 = (prow + dy) * 34 + (dx + lcol);        // mtile 0
        const int pi1 = pi0 + 16;                              // mtile 1
        const uint32_t a0 =
            (uint32_t)(pi0 * 32 + (koff0 ^ ((pi0 & 4) << 2)));
        const uint32_t a1 =
            (uint32_t)(pi1 * 32 + (koff0 ^ ((pi1 & 4) << 2)));

        uint32_t ah0[4], ah1[4];
        ldsm_x4(ah0, shi + a0);
        ldsm_x4(ah1, shi + a1);

        // B: this warp's 4 ntiles = nhalf, nhalf+2, nhalf+4, nhalf+6
        const uint4* bb =
            (const uint4*)g_bfrag + ((ks * 8 + nhalf) * 32) + lane;
        #pragma unroll
        for (int p = 0; p < 4; p++) {
            uint4 bv = __ldg(bb + 2 * p * 32);
            mma16816(d[0][p], ah0, bv.x, bv.y);   // A * Whi
            mma16816(d[1][p], ah1, bv.x, bv.y);
            mma16816(d[0][p], ah0, bv.z, bv.w);   // A * Wlo
            mma16816(d[1][p], ah1, bv.z, bv.w);
        }
    }

    // ---- epilogue: LSTM update, fully register-local per lane ----
    // ntile nhalf+2p covers n = p*16 + nhalf*8 + {2j,2j+1}  =>
    // gate p (i,f,c,o), channels ch = nhalf*8 + 2j, ch+1.
    const int ybase = y0 + prow;
    const int ch = nhalf * 8 + 2 * j;
    #pragma unroll
    for (int mt = 0; mt < 2; mt++) {
        #pragma unroll
        for (int ph = 0; ph < 2; ph++) {            // pixel row-half g / g+8
            const int xc = x0 + mt * 16 + g + ph * 8;
            const long pb = (((long)b * HH + ybase) * WW + xc) * FF;
            const int co = ph * 2;                  // quad index base

            float zi0 = d[mt][0][co]     + __ldg(bias + ch);
            float zi1 = d[mt][0][co + 1] + __ldg(bias + ch + 1);
            float zf0 = d[mt][1][co]     + __ldg(bias + 16 + ch);
            float zf1 = d[mt][1][co + 1] + __ldg(bias + 16 + ch + 1);
            float zc0 = d[mt][2][co]     + __ldg(bias + 32 + ch);
            float zc1 = d[mt][2][co + 1] + __ldg(bias + 32 + ch + 1);
            float zo0 = d[mt][3][co]     + __ldg(bias + 48 + ch);
            float zo1 = d[mt][3][co + 1] + __ldg(bias + 48 + ch + 1);

            float2 cp = *(const float2*)(c_state + pb + ch);
            float ig0 = 1.f / (1.f + __expf(-zi0));
            float ig1 = 1.f / (1.f + __expf(-zi1));
            float fg0 = 1.f / (1.f + __expf(-zf0));
            float fg1 = 1.f / (1.f + __expf(-zf1));
            float og0 = 1.f / (1.f + __expf(-zo0));
            float og1 = 1.f / (1.f + __expf(-zo1));
            float cn0 = fg0 * cp.x + ig0 * fmaxf(zc0, 0.f);
            float cn1 = fg1 * cp.y + ig1 * fmaxf(zc1, 0.f);
            float hn0 = og0 * fmaxf(cn0, 0.f);
            float hn1 = og1 * fmaxf(cn1, 0.f);

            *(float2*)(c_state + pb + ch) = make_float2(cn0, cn1);

            __half hh0 = __float2half_rn(hn0);
            __half hh1 = __float2half_rn(hn1);
            uint32_t whv = (uint32_t)__half_as_ushort(hh0) |
                           ((uint32_t)__half_as_ushort(hh1) << 16);
            *(uint32_t*)(h_out + pb + ch) = whv;
        }
    }
}

// ---------------- dense head ----------------
__global__ void dense_kernel(const __half* __restrict__ h,
                             const float* __restrict__ dw,
                             const float* __restrict__ db,
                             float* __restrict__ out)
{
    int idx = blockIdx.x * blockDim.x + threadIdx.x;
    if (idx >= BB * HH * WW) return;
    const __half* hp = h + (long)idx * FF;
    float sum = 0.f;
    #pragma unroll
    for (int k = 0; k < FF; k++) {
        sum += __half2float(hp[k]) * __ldg(dw + k);
    }
    out[idx] = sum + __ldg(db);
}

extern "C" void kernel_launch(void* const* d_in, const int* in_sizes, int n_in,
                              void* d_out, int out_size)
{
    (void)in_sizes; (void)n_in; (void)out_size;
    const float* x    = (const float*)d_in[0];
    const float* wx   = (const float*)d_in[1];
    const float* wh   = (const float*)d_in[2];
    const float* bias = (const float*)d_in[3];
    const float* dw   = (const float*)d_in[4];
    const float* db   = (const float*)d_in[5];
    float* out = (float*)d_out;

    __half* hbuf;
    float* cbuf;
    cudaGetSymbolAddress((void**)&hbuf, g_h);
    cudaGetSymbolAddress((void**)&cbuf, g_c);

    convert_x_kernel<<<2048, 256>>>(x);
    zero_state_kernel<<<512, 256>>>();
    bfrag_kernel<<<(BFRAG_WORDS + 255) / 256, 256>>>(wx, wh);

    dim3 grid(WW / TLX, HH / TLY, BB);   // (3, 24, 16) = 1152 blocks
    for (int t = 0; t < TT; t++) {
        __half* hin  = hbuf + (t & 1) * STATE_ELEMS;
        __half* hout = hbuf + ((t + 1) & 1) * STATE_ELEMS;
        lstm_step_mma<<<grid, 256, SMEM_TOTAL>>>(
            bias, hin, hout, cbuf, t);
    }

    // t=23 -> final h in buffer index 0
    int npix = BB * HH * WW;
    dense_kernel<<<(npix + 255) / 256, 256>>>(hbuf, dw, db, out);
}

// round 14
// speedup vs baseline: 1.5391x; 1.3507x over previous
#include <cuda_runtime.h>
#include <cuda_fp16.h>
#include <cstdint>
#include <math.h>

#define BB   16
#define TT   24
#define HH   96
#define WW   96
#define CIN  16
#define FF   16
#define GG   64

#define TLX  32
#define TLY  8
#define STATE_ELEMS (BB * HH * WW * FF)
#define XN (BB * TT * HH * WW * CIN)

// ---------------- device global scratch ----------------
__device__ __align__(16) __half g_x[XN];
__device__ __align__(16) __half g_h[2][STATE_ELEMS];
__device__ __align__(16) float  g_c[STATE_ELEMS];
// B fragments (single fp16 product): [kstep 18][ntile 8][lane 32] uint2 {b0,b1}
#define BFRAG_WORDS (18 * 8 * 32 * 2)   // 9216 words = 36KB, L1-resident
__device__ __align__(16) uint32_t g_bfrag[BFRAG_WORDS];

// ---------------- smem layout (bytes) ----------------
// 2 strips: x, h ; each [row 10][col 34][ci 16] fp16
// XOR-swizzled: pixel pi stores its two 16B halves at pi*32 + (half ^ ((pi&4)<<2))
#define STRIP_BYTES (10 * 34 * CIN * 2)     // 10880
#define SMEM_TOTAL  (2 * STRIP_BYTES)       // 21760

// ---------------- mma / ldmatrix helpers ----------------
__device__ __forceinline__ void mma16816(float* d, const uint32_t* a,
                                         uint32_t b0, uint32_t b1) {
    asm volatile(
        "mma.sync.aligned.m16n8k16.row.col.f32.f16.f16.f32 "
        "{%0,%1,%2,%3}, {%4,%5,%6,%7}, {%8,%9}, {%0,%1,%2,%3};"
        : "+f"(d[0]), "+f"(d[1]), "+f"(d[2]), "+f"(d[3])
        : "r"(a[0]), "r"(a[1]), "r"(a[2]), "r"(a[3]), "r"(b0), "r"(b1));
}
__device__ __forceinline__ void ldsm_x4(uint32_t* a, uint32_t addr) {
    asm volatile(
        "ldmatrix.sync.aligned.m8n8.x4.shared.b16 {%0,%1,%2,%3}, [%4];"
        : "=r"(a[0]), "=r"(a[1]), "=r"(a[2]), "=r"(a[3]) : "r"(addr));
}
__device__ __forceinline__ uint32_t smem_u32(const void* p) {
    uint32_t a;
    asm("{ .reg .u64 t; cvta.to.shared.u64 t, %1; cvt.u32.u64 %0, t; }"
        : "=r"(a) : "l"(p));
    return a;
}

// ---------------- setup kernels ----------------
__global__ void convert_x_kernel(const float* __restrict__ x) {
    for (long i = blockIdx.x * (long)blockDim.x + threadIdx.x; i < XN;
         i += (long)gridDim.x * blockDim.x) {
        g_x[i] = __float2half_rn(x[i]);
    }
}

__global__ void zero_state_kernel() {
    __half z = __float2half_rn(0.f);
    for (int i = blockIdx.x * blockDim.x + threadIdx.x; i < STATE_ELEMS;
         i += gridDim.x * blockDim.x) {
        g_h[0][i] = z;
        g_c[i] = 0.f;
    }
}

__global__ void bfrag_kernel(const float* __restrict__ wx,
                             const float* __restrict__ wh) {
    int idx = blockIdx.x * blockDim.x + threadIdx.x;
    if (idx >= BFRAG_WORDS) return;
    int reg   = idx & 1;           // 0:b0 1:b1
    int lane  = (idx >> 1) & 31;
    int nt    = (idx >> 6) & 7;
    int kstep = idx >> 9;
    int j = lane & 3;
    int n = nt * 8 + (lane >> 2);
    int k0 = reg * 8 + 2 * j;
    const float* W = (kstep < 9) ? wx : wh;
    int tap = (kstep < 9) ? kstep : kstep - 9;
    float v0 = W[(tap * 16 + k0) * 64 + n];
    float v1 = W[(tap * 16 + k0 + 1) * 64 + n];
    __half h0 = __float2half_rn(v0);
    __half h1 = __float2half_rn(v1);
    uint32_t word = (uint32_t)__half_as_ushort(h0) |
                    ((uint32_t)__half_as_ushort(h1) << 16);
    g_bfrag[idx] = word;
}

// ---------------- main step kernel ----------------
__global__ __launch_bounds__(256, 2)
void lstm_step_mma(const float* __restrict__ bias,
                   const __half* __restrict__ h_in,
                   __half* __restrict__ h_out,
                   float* __restrict__ c_state,
                   int t)
{
    extern __shared__ char smem[];
    const uint32_t sb = smem_u32(smem);
    const int tid  = threadIdx.x;
    const int wid  = tid >> 5;
    const int lane = tid & 31;
    const int x0 = blockIdx.x * TLX;
    const int y0 = blockIdx.y * TLY;
    const int b  = blockIdx.z;

    // ---- stage strips (zero halo), XOR-swizzled 16B halves ----
    {
        const long xg = ((long)(b * TT + t)) * (HH * WW * CIN);
        const long hg = ((long)b) * (HH * WW * CIN);
        #pragma unroll 1
        for (int i = tid; i < 2 * 10 * 34; i += 256) {
            int comp = i / 340;          // 0: x, 1: h
            int idx  = i - comp * 340;
            int row  = idx / 34;
            int col  = idx - row * 34;
            int y  = y0 + row - 1;
            int xc = x0 + col - 1;
            uint4 v0 = make_uint4(0, 0, 0, 0), v1 = v0;
            if ((unsigned)y < HH && (unsigned)xc < WW) {
                const __half* base = comp ? h_in : g_x;
                long off = (comp ? hg : xg) + (((long)y) * WW + xc) * CIN;
                const uint4* sp = (const uint4*)(base + off);
                v0 = sp[0];
                v1 = sp[1];
            }
            int pi = row * 34 + col;
            int sw = (pi & 4) << 2;   // 0 or 16
            char* dp = smem + comp * STRIP_BYTES + pi * 32;
            *(uint4*)(dp + (0  ^ sw)) = v0;
            *(uint4*)(dp + (16 ^ sw)) = v1;
        }
    }
    __syncthreads();

    // ---- per-warp GEMM: m32 pixels x n64 gates, K=288, SINGLE product ----
    // z = A_fp16 * W_fp16 (fp32 accum); W quant adds ~2.4e-4 RMS rel error,
    // same class as the activation quantization already present.
    const int prow = wid;                  // warp = image row within tile (0..7)
    const int g = lane >> 2;
    const int j = lane & 3;
    const int lcol  = lane & 15;           // ldmatrix pixel within m16 tile
    const int koff0 = lane & 16;           // ldmatrix k-half (bytes)

    float d[2][8][4];
    #pragma unroll
    for (int mt = 0; mt < 2; mt++)
        #pragma unroll
        for (int nt = 0; nt < 8; nt++)
            #pragma unroll
            for (int q = 0; q < 4; q++) d[mt][nt][q] = 0.f;

    // fully unrolled: with regs off the 128 cap, ptxas can pipeline the next
    // kstep's LDSM/LDG into the current MMA burst.
    #pragma unroll
    for (int ks = 0; ks < 18; ks++) {
        const int tensorSel = (ks >= 9) ? 1 : 0;
        const int tap = ks - tensorSel * 9;
        const uint32_t shi = sb + tensorSel * STRIP_BYTES;

        const int dy = tap / 3;
        const int dx = tap - dy * 3;
        const int pi0 = (prow + dy) * 34 + (dx + lcol);        // mtile 0
        const int pi1 = pi0 + 16;                              // mtile 1
        const uint32_t a0 =
            (uint32_t)(pi0 * 32 + (koff0 ^ ((pi0 & 4) << 2)));
        const uint32_t a1 =
            (uint32_t)(pi1 * 32 + (koff0 ^ ((pi1 & 4) << 2)));

        uint32_t ah0[4], ah1[4];
        ldsm_x4(ah0, shi + a0);
        ldsm_x4(ah1, shi + a1);

        const uint2* bb = (const uint2*)g_bfrag + (ks * 8) * 32 + lane;
        #pragma unroll
        for (int p = 0; p < 4; p++) {
            const int n0 = 2 * p;
            const int n1 = 2 * p + 1;
            uint2 b0 = __ldg(bb + n0 * 32);
            uint2 b1 = __ldg(bb + n1 * 32);
            mma16816(d[0][n0], ah0, b0.x, b0.y);
            mma16816(d[1][n0], ah1, b0.x, b0.y);
            mma16816(d[0][n1], ah0, b1.x, b1.y);
            mma16816(d[1][n1], ah1, b1.x, b1.y);
        }
    }

    // ---- epilogue: LSTM update, fully register-local per lane ----
    const int ybase = y0 + prow;
    #pragma unroll
    for (int mt = 0; mt < 2; mt++) {
        #pragma unroll
        for (int ph = 0; ph < 2; ph++) {            // pixel g or g+8
            const int xc = x0 + mt * 16 + g + ph * 8;
            const long pb = (((long)b * HH + ybase) * WW + xc) * FF;
            const int co = ph * 2;                  // accumulator index base
            #pragma unroll
            for (int pr = 0; pr < 2; pr++) {        // channel pair A / B
                const int ch  = pr * 8 + 2 * j;     // channels ch, ch+1
                const int ntb = pr;                 // gate ntiles: ntb, +2, +4, +6
                float zi0 = d[mt][ntb][co]       + __ldg(bias + ch);
                float zi1 = d[mt][ntb][co + 1]   + __ldg(bias + ch + 1);
                float zf0 = d[mt][ntb + 2][co]   + __ldg(bias + 16 + ch);
                float zf1 = d[mt][ntb + 2][co+1] + __ldg(bias + 16 + ch + 1);
                float zc0 = d[mt][ntb + 4][co]   + __ldg(bias + 32 + ch);
                float zc1 = d[mt][ntb + 4][co+1] + __ldg(bias + 32 + ch + 1);
                float zo0 = d[mt][ntb + 6][co]   + __ldg(bias + 48 + ch);
                float zo1 = d[mt][ntb + 6][co+1] + __ldg(bias + 48 + ch + 1);

                float2 cp = *(const float2*)(c_state + pb + ch);
                float ig0 = 1.f / (1.f + __expf(-zi0));
                float ig1 = 1.f / (1.f + __expf(-zi1));
                float fg0 = 1.f / (1.f + __expf(-zf0));
                float fg1 = 1.f / (1.f + __expf(-zf1));
                float og0 = 1.f / (1.f + __expf(-zo0));
                float og1 = 1.f / (1.f + __expf(-zo1));
                float cn0 = fg0 * cp.x + ig0 * fmaxf(zc0, 0.f);
                float cn1 = fg1 * cp.y + ig1 * fmaxf(zc1, 0.f);
                float hn0 = og0 * fmaxf(cn0, 0.f);
                float hn1 = og1 * fmaxf(cn1, 0.f);

                *(float2*)(c_state + pb + ch) = make_float2(cn0, cn1);

                __half hh0 = __float2half_rn(hn0);
                __half hh1 = __float2half_rn(hn1);
                uint32_t whv = (uint32_t)__half_as_ushort(hh0) |
                               ((uint32_t)__half_as_ushort(hh1) << 16);
                *(uint32_t*)(h_out + pb + ch) = whv;
            }
        }
    }
}

// ---------------- dense head ----------------
__global__ void dense_kernel(const __half* __restrict__ h,
                             const float* __restrict__ dw,
                             const float* __restrict__ db,
                             float* __restrict__ out)
{
    int idx = blockIdx.x * blockDim.x + threadIdx.x;
    if (idx >= BB * HH * WW) return;
    const __half* hp = h + (long)idx * FF;
    float sum = 0.f;
    #pragma unroll
    for (int k = 0; k < FF; k++) {
        sum += __half2float(hp[k]) * __ldg(dw + k);
    }
    out[idx] = sum + __ldg(db);
}

extern "C" void kernel_launch(void* const* d_in, const int* in_sizes, int n_in,
                              void* d_out, int out_size)
{
    (void)in_sizes; (void)n_in; (void)out_size;
    const float* x    = (const float*)d_in[0];
    const float* wx   = (const float*)d_in[1];
    const float* wh   = (const float*)d_in[2];
    const float* bias = (const float*)d_in[3];
    const float* dw   = (const float*)d_in[4];
    const float* db   = (const float*)d_in[5];
    float* out = (float*)d_out;

    __half* hbuf;
    float* cbuf;
    cudaGetSymbolAddress((void**)&hbuf, g_h);
    cudaGetSymbolAddress((void**)&cbuf, g_c);

    convert_x_kernel<<<2048, 256>>>(x);
    zero_state_kernel<<<512, 256>>>();
    bfrag_kernel<<<(BFRAG_WORDS + 255) / 256, 256>>>(wx, wh);

    dim3 grid(WW / TLX, HH / TLY, BB);   // (3, 12, 16)
    for (int t = 0; t < TT; t++) {
        __half* hin  = hbuf + (t & 1) * STATE_ELEMS;
        __half* hout = hbuf + ((t + 1) & 1) * STATE_ELEMS;
        lstm_step_mma<<<grid, 256, SMEM_TOTAL>>>(
            bias, hin, hout, cbuf, t);
    }

    // t=23 -> final h in buffer index 0
    int npix = BB * HH * WW;
    dense_kernel<<<(npix + 255) / 256, 256>>>(hbuf, dw, db, out);
}

// round 15
// speedup vs baseline: 1.5525x; 1.0087x over previous
#include <cuda_runtime.h>
#include <cuda_fp16.h>
#include <cstdint>
#include <math.h>

#define BB   16
#define TT   24
#define HH   96
#define WW   96
#define CIN  16
#define FF   16
#define GG   64

#define TLX  32
#define TLY  4
#define STATE_ELEMS (BB * HH * WW * FF)
#define XN (BB * TT * HH * WW * CIN)

// ---------------- device global scratch ----------------
__device__ __align__(16) __half g_x[XN];
__device__ __align__(16) __half g_h[2][STATE_ELEMS];
__device__ __align__(16) float  g_c[STATE_ELEMS];
// B fragments (single fp16 product): [kstep 18][ntile 8][lane 32] uint2 {b0,b1}
#define BFRAG_WORDS (18 * 8 * 32 * 2)   // 9216 words = 36KB, L1-resident
__device__ __align__(16) uint32_t g_bfrag[BFRAG_WORDS];

// ---------------- smem layout (bytes) ----------------
// 2 strips: x, h ; each [row 6][col 34][ci 16] fp16
// XOR-swizzled: pixel pi stores its two 16B halves at pi*32 + (half ^ ((pi&4)<<2))
#define STRIP_BYTES (6 * 34 * CIN * 2)      // 6528
#define SMEM_TOTAL  (2 * STRIP_BYTES)       // 13056

// ---------------- mma / ldmatrix helpers ----------------
__device__ __forceinline__ void mma16816(float* d, const uint32_t* a,
                                         uint32_t b0, uint32_t b1) {
    asm volatile(
        "mma.sync.aligned.m16n8k16.row.col.f32.f16.f16.f32 "
        "{%0,%1,%2,%3}, {%4,%5,%6,%7}, {%8,%9}, {%0,%1,%2,%3};"
        : "+f"(d[0]), "+f"(d[1]), "+f"(d[2]), "+f"(d[3])
        : "r"(a[0]), "r"(a[1]), "r"(a[2]), "r"(a[3]), "r"(b0), "r"(b1));
}
__device__ __forceinline__ void ldsm_x4(uint32_t* a, uint32_t addr) {
    asm volatile(
        "ldmatrix.sync.aligned.m8n8.x4.shared.b16 {%0,%1,%2,%3}, [%4];"
        : "=r"(a[0]), "=r"(a[1]), "=r"(a[2]), "=r"(a[3]) : "r"(addr));
}
__device__ __forceinline__ uint32_t smem_u32(const void* p) {
    uint32_t a;
    asm("{ .reg .u64 t; cvta.to.shared.u64 t, %1; cvt.u32.u64 %0, t; }"
        : "=r"(a) : "l"(p));
    return a;
}

// ---------------- setup kernels ----------------
__global__ void convert_x_kernel(const float* __restrict__ x) {
    for (long i = blockIdx.x * (long)blockDim.x + threadIdx.x; i < XN;
         i += (long)gridDim.x * blockDim.x) {
        g_x[i] = __float2half_rn(x[i]);
    }
}

__global__ void zero_state_kernel() {
    __half z = __float2half_rn(0.f);
    for (int i = blockIdx.x * blockDim.x + threadIdx.x; i < STATE_ELEMS;
         i += gridDim.x * blockDim.x) {
        g_h[0][i] = z;
        g_c[i] = 0.f;
    }
}

__global__ void bfrag_kernel(const float* __restrict__ wx,
                             const float* __restrict__ wh) {
    int idx = blockIdx.x * blockDim.x + threadIdx.x;
    if (idx >= BFRAG_WORDS) return;
    int reg   = idx & 1;           // 0:b0 1:b1
    int lane  = (idx >> 1) & 31;
    int nt    = (idx >> 6) & 7;
    int kstep = idx >> 9;
    int j = lane & 3;
    int n = nt * 8 + (lane >> 2);
    int k0 = reg * 8 + 2 * j;
    const float* W = (kstep < 9) ? wx : wh;
    int tap = (kstep < 9) ? kstep : kstep - 9;
    float v0 = W[(tap * 16 + k0) * 64 + n];
    float v1 = W[(tap * 16 + k0 + 1) * 64 + n];
    __half h0 = __float2half_rn(v0);
    __half h1 = __float2half_rn(v1);
    uint32_t word = (uint32_t)__half_as_ushort(h0) |
                    ((uint32_t)__half_as_ushort(h1) << 16);
    g_bfrag[idx] = word;
}

// ---------------- main step kernel ----------------
// 256 thr = 8 warps; warp = (image row, N-half): m32 x n32, single product.
// 3 blocks/SM -> 24 warps/SM = 6 per SMSP to cover per-kstep load windows.
__global__ __launch_bounds__(256, 3)
void lstm_step_mma(const float* __restrict__ bias,
                   const __half* __restrict__ h_in,
                   __half* __restrict__ h_out,
                   float* __restrict__ c_state,
                   int t)
{
    extern __shared__ char smem[];
    const uint32_t sb = smem_u32(smem);
    const int tid  = threadIdx.x;
    const int wid  = tid >> 5;
    const int lane = tid & 31;
    const int x0 = blockIdx.x * TLX;
    const int y0 = blockIdx.y * TLY;
    const int b  = blockIdx.z;

    // ---- stage strips (zero halo), XOR-swizzled 16B halves ----
    {
        const long xg = ((long)(b * TT + t)) * (HH * WW * CIN);
        const long hg = ((long)b) * (HH * WW * CIN);
        #pragma unroll 1
        for (int i = tid; i < 2 * 6 * 34; i += 256) {
            int comp = i / 204;          // 0: x, 1: h
            int idx  = i - comp * 204;
            int row  = idx / 34;
            int col  = idx - row * 34;
            int y  = y0 + row - 1;
            int xc = x0 + col - 1;
            uint4 v0 = make_uint4(0, 0, 0, 0), v1 = v0;
            if ((unsigned)y < HH && (unsigned)xc < WW) {
                const __half* base = comp ? h_in : g_x;
                long off = (comp ? hg : xg) + (((long)y) * WW + xc) * CIN;
                const uint4* sp = (const uint4*)(base + off);
                v0 = sp[0];
                v1 = sp[1];
            }
            int pi = row * 34 + col;
            int sw = (pi & 4) << 2;   // 0 or 16
            char* dp = smem + comp * STRIP_BYTES + pi * 32;
            *(uint4*)(dp + (0  ^ sw)) = v0;
            *(uint4*)(dp + (16 ^ sw)) = v1;
        }
    }
    __syncthreads();

    // ---- per-warp GEMM: m32 x n32, K=288, single fp16 product ----
    const int prow  = wid >> 1;            // image row within tile (0..3)
    const int nhalf = wid & 1;             // N-half: even/odd ntiles
    const int g = lane >> 2;
    const int j = lane & 3;
    const int lcol  = lane & 15;           // ldmatrix pixel within m16 tile
    const int koff0 = lane & 16;           // ldmatrix k-half (bytes)

    float d[2][4][4];                      // [mtile][gate p][quad]
    #pragma unroll
    for (int mt = 0; mt < 2; mt++)
        #pragma unroll
        for (int p = 0; p < 4; p++)
            #pragma unroll
            for (int q = 0; q < 4; q++) d[mt][p][q] = 0.f;

    // warp phase rotation: desynchronize warps sharing an SMSP
    int phase = wid * 5;
    if (phase >= 18) phase -= 18;          // {0,5,10,15,2,7,12,17}

    #pragma unroll 1
    for (int kk = 0; kk < 18; kk++) {
        int ks = kk + phase;
        if (ks >= 18) ks -= 18;
        const int tensorSel = (ks >= 9) ? 1 : 0;
        const int tap = ks - tensorSel * 9;
        const uint32_t shi = sb + tensorSel * STRIP_BYTES;

        const int dy = tap / 3;
        const int dx = tap - dy * 3;
        const int pi0 = (prow + dy) * 34 + (dx + lcol);        // mtile 0
        const int pi1 = pi0 + 16;                              // mtile 1
        const uint32_t a0 =
            (uint32_t)(pi0 * 32 + (koff0 ^ ((pi0 & 4) << 2)));
        const uint32_t a1 =
            (uint32_t)(pi1 * 32 + (koff0 ^ ((pi1 & 4) << 2)));

        uint32_t ah0[4], ah1[4];
        ldsm_x4(ah0, shi + a0);
        ldsm_x4(ah1, shi + a1);

        // B: this warp's 4 ntiles = nhalf, nhalf+2, nhalf+4, nhalf+6
        const uint2* bb =
            (const uint2*)g_bfrag + ((ks * 8 + nhalf) * 32) + lane;
        #pragma unroll
        for (int p = 0; p < 4; p++) {
            uint2 bv = __ldg(bb + 2 * p * 32);
            mma16816(d[0][p], ah0, bv.x, bv.y);
            mma16816(d[1][p], ah1, bv.x, bv.y);
        }
    }

    // ---- epilogue: LSTM update, fully register-local per lane ----
    // ntile nhalf+2p covers gate p (i,f,c,o), channels ch = nhalf*8+2j, ch+1.
    const int ybase = y0 + prow;
    const int ch = nhalf * 8 + 2 * j;
    #pragma unroll
    for (int mt = 0; mt < 2; mt++) {
        #pragma unroll
        for (int ph = 0; ph < 2; ph++) {            // pixel row-half g / g+8
            const int xc = x0 + mt * 16 + g + ph * 8;
            const long pb = (((long)b * HH + ybase) * WW + xc) * FF;
            const int co = ph * 2;                  // quad index base

            float zi0 = d[mt][0][co]     + __ldg(bias + ch);
            float zi1 = d[mt][0][co + 1] + __ldg(bias + ch + 1);
            float zf0 = d[mt][1][co]     + __ldg(bias + 16 + ch);
            float zf1 = d[mt][1][co + 1] + __ldg(bias + 16 + ch + 1);
            float zc0 = d[mt][2][co]     + __ldg(bias + 32 + ch);
            float zc1 = d[mt][2][co + 1] + __ldg(bias + 32 + ch + 1);
            float zo0 = d[mt][3][co]     + __ldg(bias + 48 + ch);
            float zo1 = d[mt][3][co + 1] + __ldg(bias + 48 + ch + 1);

            float2 cp = *(const float2*)(c_state + pb + ch);
            float ig0 = 1.f / (1.f + __expf(-zi0));
            float ig1 = 1.f / (1.f + __expf(-zi1));
            float fg0 = 1.f / (1.f + __expf(-zf0));
            float fg1 = 1.f / (1.f + __expf(-zf1));
            float og0 = 1.f / (1.f + __expf(-zo0));
            float og1 = 1.f / (1.f + __expf(-zo1));
            float cn0 = fg0 * cp.x + ig0 * fmaxf(zc0, 0.f);
            float cn1 = fg1 * cp.y + ig1 * fmaxf(zc1, 0.f);
            float hn0 = og0 * fmaxf(cn0, 0.f);
            float hn1 = og1 * fmaxf(cn1, 0.f);

            *(float2*)(c_state + pb + ch) = make_float2(cn0, cn1);

            __half hh0 = __float2half_rn(hn0);
            __half hh1 = __float2half_rn(hn1);
            uint32_t whv = (uint32_t)__half_as_ushort(hh0) |
                           ((uint32_t)__half_as_ushort(hh1) << 16);
            *(uint32_t*)(h_out + pb + ch) = whv;
        }
    }
}

// ---------------- dense head ----------------
__global__ void dense_kernel(const __half* __restrict__ h,
                             const float* __restrict__ dw,
                             const float* __restrict__ db,
                             float* __restrict__ out)
{
    int idx = blockIdx.x * blockDim.x + threadIdx.x;
    if (idx >= BB * HH * WW) return;
    const __half* hp = h + (long)idx * FF;
    float sum = 0.f;
    #pragma unroll
    for (int k = 0; k < FF; k++) {
        sum += __half2float(hp[k]) * __ldg(dw + k);
    }
    out[idx] = sum + __ldg(db);
}

extern "C" void kernel_launch(void* const* d_in, const int* in_sizes, int n_in,
                              void* d_out, int out_size)
{
    (void)in_sizes; (void)n_in; (void)out_size;
    const float* x    = (const float*)d_in[0];
    const float* wx   = (const float*)d_in[1];
    const float* wh   = (const float*)d_in[2];
    const float* bias = (const float*)d_in[3];
    const float* dw   = (const float*)d_in[4];
    const float* db   = (const float*)d_in[5];
    float* out = (float*)d_out;

    __half* hbuf;
    float* cbuf;
    cudaGetSymbolAddress((void**)&hbuf, g_h);
    cudaGetSymbolAddress((void**)&cbuf, g_c);

    convert_x_kernel<<<2048, 256>>>(x);
    zero_state_kernel<<<512, 256>>>();
    bfrag_kernel<<<(BFRAG_WORDS + 255) / 256, 256>>>(wx, wh);

    dim3 grid(WW / TLX, HH / TLY, BB);   // (3, 24, 16) = 1152 blocks
    for (int t = 0; t < TT; t++) {
        __half* hin  = hbuf + (t & 1) * STATE_ELEMS;
        __half* hout = hbuf + ((t + 1) & 1) * STATE_ELEMS;
        lstm_step_mma<<<grid, 256, SMEM_TOTAL>>>(
            bias, hin, hout, cbuf, t);
    }

    // t=23 -> final h in buffer index 0
    int npix = BB * HH * WW;
    dense_kernel<<<(npix + 255) / 256, 256>>>(hbuf, dw, db, out);
}

// round 16
// speedup vs baseline: 1.6381x; 1.0551x over previous
#include <cuda_runtime.h>
#include <cuda_fp16.h>
#include <cstdint>
#include <math.h>

#define BB   16
#define TT   24
#define HH   96
#define WW   96
#define CIN  16
#define FF   16
#define GG   64

#define TLX  32
#define TLY  4
#define STATE_ELEMS (BB * HH * WW * FF)
#define XN (BB * TT * HH * WW * CIN)

// ---------------- device global scratch ----------------
__device__ __align__(16) __half g_x[XN];
__device__ __align__(16) __half g_h[2][STATE_ELEMS];
__device__ __align__(16) float  g_c[STATE_ELEMS];
// B fragments (single fp16 product): [kstep 18][ntile 8][lane 32] uint2 {b0,b1}
#define BFRAG_WORDS (18 * 8 * 32 * 2)   // 9216 words = 36KB, L1-resident
__device__ __align__(16) uint32_t g_bfrag[BFRAG_WORDS];

// ---------------- smem layout (bytes) ----------------
// 2 strips: x, h ; each [row 6][col 34][ci 16] fp16
// XOR-swizzled: pixel pi stores its two 16B halves at pi*32 + (half ^ ((pi&4)<<2))
#define STRIP_BYTES (6 * 34 * CIN * 2)      // 6528
#define SMEM_TOTAL  (2 * STRIP_BYTES)       // 13056

// ---------------- mma / ldmatrix helpers ----------------
__device__ __forceinline__ void mma16816(float* d, const uint32_t* a,
                                         uint32_t b0, uint32_t b1) {
    asm volatile(
        "mma.sync.aligned.m16n8k16.row.col.f32.f16.f16.f32 "
        "{%0,%1,%2,%3}, {%4,%5,%6,%7}, {%8,%9}, {%0,%1,%2,%3};"
        : "+f"(d[0]), "+f"(d[1]), "+f"(d[2]), "+f"(d[3])
        : "r"(a[0]), "r"(a[1]), "r"(a[2]), "r"(a[3]), "r"(b0), "r"(b1));
}
__device__ __forceinline__ void ldsm_x4(uint32_t* a, uint32_t addr) {
    asm volatile(
        "ldmatrix.sync.aligned.m8n8.x4.shared.b16 {%0,%1,%2,%3}, [%4];"
        : "=r"(a[0]), "=r"(a[1]), "=r"(a[2]), "=r"(a[3]) : "r"(addr));
}
__device__ __forceinline__ uint32_t smem_u32(const void* p) {
    uint32_t a;
    asm("{ .reg .u64 t; cvta.to.shared.u64 t, %1; cvt.u32.u64 %0, t; }"
        : "=r"(a) : "l"(p));
    return a;
}

// ---------------- setup kernels ----------------
__global__ void convert_x_kernel(const float* __restrict__ x) {
    for (long i = blockIdx.x * (long)blockDim.x + threadIdx.x; i < XN;
         i += (long)gridDim.x * blockDim.x) {
        g_x[i] = __float2half_rn(x[i]);
    }
}

__global__ void zero_state_kernel() {
    __half z = __float2half_rn(0.f);
    for (int i = blockIdx.x * blockDim.x + threadIdx.x; i < STATE_ELEMS;
         i += gridDim.x * blockDim.x) {
        g_h[0][i] = z;
        g_c[i] = 0.f;
    }
}

__global__ void bfrag_kernel(const float* __restrict__ wx,
                             const float* __restrict__ wh) {
    int idx = blockIdx.x * blockDim.x + threadIdx.x;
    if (idx >= BFRAG_WORDS) return;
    int reg   = idx & 1;           // 0:b0 1:b1
    int lane  = (idx >> 1) & 31;
    int nt    = (idx >> 6) & 7;
    int kstep = idx >> 9;
    int j = lane & 3;
    int n = nt * 8 + (lane >> 2);
    int k0 = reg * 8 + 2 * j;
    const float* W = (kstep < 9) ? wx : wh;
    int tap = (kstep < 9) ? kstep : kstep - 9;
    float v0 = W[(tap * 16 + k0) * 64 + n];
    float v1 = W[(tap * 16 + k0 + 1) * 64 + n];
    __half h0 = __float2half_rn(v0);
    __half h1 = __float2half_rn(v1);
    uint32_t word = (uint32_t)__half_as_ushort(h0) |
                    ((uint32_t)__half_as_ushort(h1) << 16);
    g_bfrag[idx] = word;
}

// ---------------- main step kernel ----------------
// 256 thr = 8 warps; warp = (image row, N-half): m32 x n32, single product.
// 3 blocks/SM -> 24 warps/SM = 6 per SMSP. Fully unrolled ksteps: tap offsets
// are compile-time, killing the per-kstep div/mod/branch ALU stream.
__global__ __launch_bounds__(256, 3)
void lstm_step_mma(const float* __restrict__ bias,
                   const __half* __restrict__ h_in,
                   __half* __restrict__ h_out,
                   float* __restrict__ c_state,
                   int t)
{
    extern __shared__ char smem[];
    const uint32_t sb = smem_u32(smem);
    const int tid  = threadIdx.x;
    const int wid  = tid >> 5;
    const int lane = tid & 31;
    const int x0 = blockIdx.x * TLX;
    const int y0 = blockIdx.y * TLY;
    const int b  = blockIdx.z;

    // ---- stage strips (zero halo), XOR-swizzled 16B halves ----
    {
        const long xg = ((long)(b * TT + t)) * (HH * WW * CIN);
        const long hg = ((long)b) * (HH * WW * CIN);
        #pragma unroll 1
        for (int i = tid; i < 2 * 6 * 34; i += 256) {
            int comp = i / 204;          // 0: x, 1: h
            int idx  = i - comp * 204;
            int row  = idx / 34;
            int col  = idx - row * 34;
            int y  = y0 + row - 1;
            int xc = x0 + col - 1;
            uint4 v0 = make_uint4(0, 0, 0, 0), v1 = v0;
            if ((unsigned)y < HH && (unsigned)xc < WW) {
                const __half* base = comp ? h_in : g_x;
                long off = (comp ? hg : xg) + (((long)y) * WW + xc) * CIN;
                const uint4* sp = (const uint4*)(base + off);
                v0 = sp[0];
                v1 = sp[1];
            }
            int pi = row * 34 + col;
            int sw = (pi & 4) << 2;   // 0 or 16
            char* dp = smem + comp * STRIP_BYTES + pi * 32;
            *(uint4*)(dp + (0  ^ sw)) = v0;
            *(uint4*)(dp + (16 ^ sw)) = v1;
        }
    }
    __syncthreads();

    // ---- per-warp GEMM: m32 x n32, K=288, single fp16 product ----
    const int prow  = wid >> 1;            // image row within tile (0..3)
    const int nhalf = wid & 1;             // N-half: even/odd ntiles
    const int g = lane >> 2;
    const int j = lane & 3;
    const int lcol  = lane & 15;           // ldmatrix pixel within m16 tile
    const int koff0 = lane & 16;           // ldmatrix k-half (bytes)

    float d[2][4][4];                      // [mtile][gate p][quad]
    #pragma unroll
    for (int mt = 0; mt < 2; mt++)
        #pragma unroll
        for (int p = 0; p < 4; p++)
            #pragma unroll
            for (int q = 0; q < 4; q++) d[mt][p][q] = 0.f;

    // base pixel index for tap (0,0): everything else is a constant offset
    const int pibase = prow * 34 + lcol;

    #pragma unroll
    for (int ks = 0; ks < 18; ks++) {
        const int tensorSel = (ks >= 9) ? 1 : 0;
        const int tap = ks - tensorSel * 9;
        const int dy = tap / 3;            // compile-time
        const int dx = tap - dy * 3;       // compile-time
        const uint32_t shi = sb + tensorSel * STRIP_BYTES;

        const int pi0 = pibase + dy * 34 + dx;                 // mtile 0
        const int pi1 = pi0 + 16;                              // mtile 1
        const uint32_t a0 =
            (uint32_t)(pi0 * 32 + (koff0 ^ ((pi0 & 4) << 2)));
        const uint32_t a1 =
            (uint32_t)(pi1 * 32 + (koff0 ^ ((pi1 & 4) << 2)));

        uint32_t ah0[4], ah1[4];
        ldsm_x4(ah0, shi + a0);
        ldsm_x4(ah1, shi + a1);

        // B: this warp's 4 ntiles = nhalf, nhalf+2, nhalf+4, nhalf+6
        const uint2* bb =
            (const uint2*)g_bfrag + ((ks * 8 + nhalf) * 32) + lane;
        #pragma unroll
        for (int p = 0; p < 4; p++) {
            uint2 bv = __ldg(bb + 2 * p * 32);
            mma16816(d[0][p], ah0, bv.x, bv.y);
            mma16816(d[1][p], ah1, bv.x, bv.y);
        }
    }

    // ---- epilogue: LSTM update, fully register-local per lane ----
    // ntile nhalf+2p covers gate p (i,f,c,o), channels ch = nhalf*8+2j, ch+1.
    const int ybase = y0 + prow;
    const int ch = nhalf * 8 + 2 * j;
    #pragma unroll
    for (int mt = 0; mt < 2; mt++) {
        #pragma unroll
        for (int ph = 0; ph < 2; ph++) {            // pixel row-half g / g+8
            const int xc = x0 + mt * 16 + g + ph * 8;
            const long pb = (((long)b * HH + ybase) * WW + xc) * FF;
            const int co = ph * 2;                  // quad index base

            float zi0 = d[mt][0][co]     + __ldg(bias + ch);
            float zi1 = d[mt][0][co + 1] + __ldg(bias + ch + 1);
            float zf0 = d[mt][1][co]     + __ldg(bias + 16 + ch);
            float zf1 = d[mt][1][co + 1] + __ldg(bias + 16 + ch + 1);
            float zc0 = d[mt][2][co]     + __ldg(bias + 32 + ch);
            float zc1 = d[mt][2][co + 1] + __ldg(bias + 32 + ch + 1);
            float zo0 = d[mt][3][co]     + __ldg(bias + 48 + ch);
            float zo1 = d[mt][3][co + 1] + __ldg(bias + 48 + ch + 1);

            float2 cp = *(const float2*)(c_state + pb + ch);
            float ig0 = 1.f / (1.f + __expf(-zi0));
            float ig1 = 1.f / (1.f + __expf(-zi1));
            float fg0 = 1.f / (1.f + __expf(-zf0));
            float fg1 = 1.f / (1.f + __expf(-zf1));
            float og0 = 1.f / (1.f + __expf(-zo0));
            float og1 = 1.f / (1.f + __expf(-zo1));
            float cn0 = fg0 * cp.x + ig0 * fmaxf(zc0, 0.f);
            float cn1 = fg1 * cp.y + ig1 * fmaxf(zc1, 0.f);
            float hn0 = og0 * fmaxf(cn0, 0.f);
            float hn1 = og1 * fmaxf(cn1, 0.f);

            *(float2*)(c_state + pb + ch) = make_float2(cn0, cn1);

            __half hh0 = __float2half_rn(hn0);
            __half hh1 = __float2half_rn(hn1);
            uint32_t whv = (uint32_t)__half_as_ushort(hh0) |
                           ((uint32_t)__half_as_ushort(hh1) << 16);
            *(uint32_t*)(h_out + pb + ch) = whv;
        }
    }
}

// ---------------- dense head ----------------
__global__ void dense_kernel(const __half* __restrict__ h,
                             const float* __restrict__ dw,
                             const float* __restrict__ db,
                             float* __restrict__ out)
{
    int idx = blockIdx.x * blockDim.x + threadIdx.x;
    if (idx >= BB * HH * WW) return;
    const __half* hp = h + (long)idx * FF;
    float sum = 0.f;
    #pragma unroll
    for (int k = 0; k < FF; k++) {
        sum += __half2float(hp[k]) * __ldg(dw + k);
    }
    out[idx] = sum + __ldg(db);
}

extern "C" void kernel_launch(void* const* d_in, const int* in_sizes, int n_in,
                              void* d_out, int out_size)
{
    (void)in_sizes; (void)n_in; (void)out_size;
    const float* x    = (const float*)d_in[0];
    const float* wx   = (const float*)d_in[1];
    const float* wh   = (const float*)d_in[2];
    const float* bias = (const float*)d_in[3];
    const float* dw   = (const float*)d_in[4];
    const float* db   = (const float*)d_in[5];
    float* out = (float*)d_out;

    __half* hbuf;
    float* cbuf;
    cudaGetSymbolAddress((void**)&hbuf, g_h);
    cudaGetSymbolAddress((void**)&cbuf, g_c);

    convert_x_kernel<<<2048, 256>>>(x);
    zero_state_kernel<<<512, 256>>>();
    bfrag_kernel<<<(BFRAG_WORDS + 255) / 256, 256>>>(wx, wh);

    dim3 grid(WW / TLX, HH / TLY, BB);   // (3, 24, 16) = 1152 blocks
    for (int t = 0; t < TT; t++) {
        __half* hin  = hbuf + (t & 1) * STATE_ELEMS;
        __half* hout = hbuf + ((t + 1) & 1) * STATE_ELEMS;
        lstm_step_mma<<<grid, 256, SMEM_TOTAL>>>(
            bias, hin, hout, cbuf, t);
    }

    // t=23 -> final h in buffer index 0
    int npix = BB * HH * WW;
    dense_kernel<<<(npix + 255) / 256, 256>>>(hbuf, dw, db, out);
}

// round 17
// speedup vs baseline: 1.6806x; 1.0260x over previous
#include <cuda_runtime.h>
#include <cuda_fp16.h>
#include <cstdint>
#include <math.h>

#define BB   16
#define TT   24
#define HH   96
#define WW   96
#define CIN  16
#define FF   16
#define GG   64

#define TLX  32
#define TLY  4
#define STATE_ELEMS (BB * HH * WW * FF)
#define XN (BB * TT * HH * WW * CIN)

// ---------------- device global scratch ----------------
__device__ __align__(16) __half g_x[XN];
__device__ __align__(16) __half g_h[2][STATE_ELEMS];
__device__ __align__(16) float  g_c[STATE_ELEMS];
// B fragments (single fp16 product): [kstep 18][ntile 8][lane 32] uint2 {b0,b1}
#define BFRAG_WORDS (18 * 8 * 32 * 2)   // 9216 words = 36KB, L1-resident
__device__ __align__(16) uint32_t g_bfrag[BFRAG_WORDS];

// ---------------- smem layout (bytes) ----------------
// 2 strips: x, h ; each [row 6][col 34][ci 16] fp16
// XOR-swizzled: pixel pi stores its two 16B halves at pi*32 + (half ^ ((pi&4)<<2))
#define STRIP_BYTES (6 * 34 * CIN * 2)      // 6528
#define SMEM_TOTAL  (2 * STRIP_BYTES)       // 13056

// ---------------- mma / ldmatrix helpers ----------------
__device__ __forceinline__ void mma16816(float* d, const uint32_t* a,
                                         uint32_t b0, uint32_t b1) {
    asm volatile(
        "mma.sync.aligned.m16n8k16.row.col.f32.f16.f16.f32 "
        "{%0,%1,%2,%3}, {%4,%5,%6,%7}, {%8,%9}, {%0,%1,%2,%3};"
        : "+f"(d[0]), "+f"(d[1]), "+f"(d[2]), "+f"(d[3])
        : "r"(a[0]), "r"(a[1]), "r"(a[2]), "r"(a[3]), "r"(b0), "r"(b1));
}
__device__ __forceinline__ void ldsm_x4(uint32_t* a, uint32_t addr) {
    asm volatile(
        "ldmatrix.sync.aligned.m8n8.x4.shared.b16 {%0,%1,%2,%3}, [%4];"
        : "=r"(a[0]), "=r"(a[1]), "=r"(a[2]), "=r"(a[3]) : "r"(addr));
}
__device__ __forceinline__ uint32_t smem_u32(const void* p) {
    uint32_t a;
    asm("{ .reg .u64 t; cvta.to.shared.u64 t, %1; cvt.u32.u64 %0, t; }"
        : "=r"(a) : "l"(p));
    return a;
}

// ---------------- setup kernels ----------------
__global__ void convert_x_kernel(const float* __restrict__ x) {
    for (long i = blockIdx.x * (long)blockDim.x + threadIdx.x; i < XN;
         i += (long)gridDim.x * blockDim.x) {
        g_x[i] = __float2half_rn(x[i]);
    }
}

__global__ void zero_state_kernel() {
    __half z = __float2half_rn(0.f);
    for (int i = blockIdx.x * blockDim.x + threadIdx.x; i < STATE_ELEMS;
         i += gridDim.x * blockDim.x) {
        g_h[0][i] = z;
        g_c[i] = 0.f;
    }
}

__global__ void bfrag_kernel(const float* __restrict__ wx,
                             const float* __restrict__ wh) {
    int idx = blockIdx.x * blockDim.x + threadIdx.x;
    if (idx >= BFRAG_WORDS) return;
    int reg   = idx & 1;           // 0:b0 1:b1
    int lane  = (idx >> 1) & 31;
    int nt    = (idx >> 6) & 7;
    int kstep = idx >> 9;
    int j = lane & 3;
    int n = nt * 8 + (lane >> 2);
    int k0 = reg * 8 + 2 * j;
    const float* W = (kstep < 9) ? wx : wh;
    int tap = (kstep < 9) ? kstep : kstep - 9;
    float v0 = W[(tap * 16 + k0) * 64 + n];
    float v1 = W[(tap * 16 + k0 + 1) * 64 + n];
    __half h0 = __float2half_rn(v0);
    __half h1 = __float2half_rn(v1);
    uint32_t word = (uint32_t)__half_as_ushort(h0) |
                    ((uint32_t)__half_as_ushort(h1) << 16);
    g_bfrag[idx] = word;
}

// ---------------- main step kernel ----------------
// 256 thr = 8 warps; warp = (image row, N-half): m32 x n32, single product.
// 4 blocks/SM -> 32 warps/SM = 8 per SMSP; rolled divide-free tap loop keeps
// regs <= 64 so the 4-block occupancy actually materializes.
__global__ __launch_bounds__(256, 4)
void lstm_step_mma(const float* __restrict__ bias,
                   const __half* __restrict__ h_in,
                   __half* __restrict__ h_out,
                   float* __restrict__ c_state,
                   int t)
{
    extern __shared__ char smem[];
    const uint32_t sb = smem_u32(smem);
    const int tid  = threadIdx.x;
    const int wid  = tid >> 5;
    const int lane = tid & 31;
    const int x0 = blockIdx.x * TLX;
    const int y0 = blockIdx.y * TLY;
    const int b  = blockIdx.z;

    // ---- stage strips (zero halo), XOR-swizzled 16B halves ----
    {
        const long xg = ((long)(b * TT + t)) * (HH * WW * CIN);
        const long hg = ((long)b) * (HH * WW * CIN);
        #pragma unroll 1
        for (int i = tid; i < 2 * 6 * 34; i += 256) {
            int comp = i / 204;          // 0: x, 1: h
            int idx  = i - comp * 204;
            int row  = idx / 34;
            int col  = idx - row * 34;
            int y  = y0 + row - 1;
            int xc = x0 + col - 1;
            uint4 v0 = make_uint4(0, 0, 0, 0), v1 = v0;
            if ((unsigned)y < HH && (unsigned)xc < WW) {
                const __half* base = comp ? h_in : g_x;
                long off = (comp ? hg : xg) + (((long)y) * WW + xc) * CIN;
                const uint4* sp = (const uint4*)(base + off);
                v0 = sp[0];
                v1 = sp[1];
            }
            int pi = row * 34 + col;
            int sw = (pi & 4) << 2;   // 0 or 16
            char* dp = smem + comp * STRIP_BYTES + pi * 32;
            *(uint4*)(dp + (0  ^ sw)) = v0;
            *(uint4*)(dp + (16 ^ sw)) = v1;
        }
    }
    __syncthreads();

    // ---- per-warp GEMM: m32 x n32, K=288, single fp16 product ----
    const int prow  = wid >> 1;            // image row within tile (0..3)
    const int nhalf = wid & 1;             // N-half: even/odd ntiles
    const int g = lane >> 2;
    const int j = lane & 3;
    const int lcol  = lane & 15;           // ldmatrix pixel within m16 tile
    const int koff0 = lane & 16;           // ldmatrix k-half (bytes)

    float d[2][4][4];                      // [mtile][gate p][quad]
    #pragma unroll
    for (int mt = 0; mt < 2; mt++)
        #pragma unroll
        for (int p = 0; p < 4; p++)
            #pragma unroll
            for (int q = 0; q < 4; q++) d[mt][p][q] = 0.f;

    const int pibase = prow * 34 + lcol;   // pixel index of tap (0,0)

    // divide-free tap loops: tensor x dy (rolled) x dx (unrolled 3)
    #pragma unroll 1
    for (int ts = 0; ts < 2; ts++) {
        const uint32_t shi = sb + ts * STRIP_BYTES;
        const uint2* bt =
            (const uint2*)g_bfrag + ((ts * 72 + nhalf) * 32) + lane;
        #pragma unroll 1
        for (int dy = 0; dy < 3; dy++) {
            const int pirow = pibase + dy * 34;
            const uint2* brow = bt + dy * 3 * 256;
            #pragma unroll
            for (int dx = 0; dx < 3; dx++) {
                const int pi0 = pirow + dx;
                const uint32_t a0 =
                    (uint32_t)(pi0 * 32 + (koff0 ^ ((pi0 & 4) << 2)));
                const uint32_t a1 = a0 + 512;   // pi0+16: same swizzle bit

                uint32_t ah0[4], ah1[4];
                ldsm_x4(ah0, shi + a0);
                ldsm_x4(ah1, shi + a1);

                const uint2* bb = brow + dx * 256;
                #pragma unroll
                for (int p = 0; p < 4; p++) {
                    uint2 bv = __ldg(bb + 2 * p * 32);
                    mma16816(d[0][p], ah0, bv.x, bv.y);
                    mma16816(d[1][p], ah1, bv.x, bv.y);
                }
            }
        }
    }

    // ---- epilogue: LSTM update, fully register-local per lane ----
    // ntile nhalf+2p covers gate p (i,f,c,o), channels ch = nhalf*8+2j, ch+1.
    const int ybase = y0 + prow;
    const int ch = nhalf * 8 + 2 * j;
    #pragma unroll
    for (int mt = 0; mt < 2; mt++) {
        #pragma unroll
        for (int ph = 0; ph < 2; ph++) {            // pixel row-half g / g+8
            const int xc = x0 + mt * 16 + g + ph * 8;
            const long pb = (((long)b * HH + ybase) * WW + xc) * FF;
            const int co = ph * 2;                  // quad index base

            float zi0 = d[mt][0][co]     + __ldg(bias + ch);
            float zi1 = d[mt][0][co + 1] + __ldg(bias + ch + 1);
            float zf0 = d[mt][1][co]     + __ldg(bias + 16 + ch);
            float zf1 = d[mt][1][co + 1] + __ldg(bias + 16 + ch + 1);
            float zc0 = d[mt][2][co]     + __ldg(bias + 32 + ch);
            float zc1 = d[mt][2][co + 1] + __ldg(bias + 32 + ch + 1);
            float zo0 = d[mt][3][co]     + __ldg(bias + 48 + ch);
            float zo1 = d[mt][3][co + 1] + __ldg(bias + 48 + ch + 1);

            float2 cp = *(const float2*)(c_state + pb + ch);
            float ig0 = 1.f / (1.f + __expf(-zi0));
            float ig1 = 1.f / (1.f + __expf(-zi1));
            float fg0 = 1.f / (1.f + __expf(-zf0));
            float fg1 = 1.f / (1.f + __expf(-zf1));
            float og0 = 1.f / (1.f + __expf(-zo0));
            float og1 = 1.f / (1.f + __expf(-zo1));
            float cn0 = fg0 * cp.x + ig0 * fmaxf(zc0, 0.f);
            float cn1 = fg1 * cp.y + ig1 * fmaxf(zc1, 0.f);
            float hn0 = og0 * fmaxf(cn0, 0.f);
            float hn1 = og1 * fmaxf(cn1, 0.f);

            *(float2*)(c_state + pb + ch) = make_float2(cn0, cn1);

            __half hh0 = __float2half_rn(hn0);
            __half hh1 = __float2half_rn(hn1);
            uint32_t whv = (uint32_t)__half_as_ushort(hh0) |
                           ((uint32_t)__half_as_ushort(hh1) << 16);
            *(uint32_t*)(h_out + pb + ch) = whv;
        }
    }
}

// ---------------- dense head ----------------
__global__ void dense_kernel(const __half* __restrict__ h,
                             const float* __restrict__ dw,
                             const float* __restrict__ db,
                             float* __restrict__ out)
{
    int idx = blockIdx.x * blockDim.x + threadIdx.x;
    if (idx >= BB * HH * WW) return;
    const __half* hp = h + (long)idx * FF;
    float sum = 0.f;
    #pragma unroll
    for (int k = 0; k < FF; k++) {
        sum += __half2float(hp[k]) * __ldg(dw + k);
    }
    out[idx] = sum + __ldg(db);
}

extern "C" void kernel_launch(void* const* d_in, const int* in_sizes, int n_in,
                              void* d_out, int out_size)
{
    (void)in_sizes; (void)n_in; (void)out_size;
    const float* x    = (const float*)d_in[0];
    const float* wx   = (const float*)d_in[1];
    const float* wh   = (const float*)d_in[2];
    const float* bias = (const float*)d_in[3];
    const float* dw   = (const float*)d_in[4];
    const float* db   = (const float*)d_in[5];
    float* out = (float*)d_out;

    __half* hbuf;
    float* cbuf;
    cudaGetSymbolAddress((void**)&hbuf, g_h);
    cudaGetSymbolAddress((void**)&cbuf, g_c);

    convert_x_kernel<<<2048, 256>>>(x);
    zero_state_kernel<<<512, 256>>>();
    bfrag_kernel<<<(BFRAG_WORDS + 255) / 256, 256>>>(wx, wh);

    dim3 grid(WW / TLX, HH / TLY, BB);   // (3, 24, 16) = 1152 blocks
    for (int t = 0; t < TT; t++) {
        __half* hin  = hbuf + (t & 1) * STATE_ELEMS;
        __half* hout = hbuf + ((t + 1) & 1) * STATE_ELEMS;
        lstm_step_mma<<<grid, 256, SMEM_TOTAL>>>(
            bias, hin, hout, cbuf, t);
    }

    // t=23 -> final h in buffer index 0
    int npix = BB * HH * WW;
    dense_kernel<<<(npix + 255) / 256, 256>>>(hbuf, dw, db, out);
}